// round 1
// baseline (speedup 1.0000x reference)
#include <cuda_runtime.h>
#include <mma.h>
#include <cstdint>
#include <cstddef>

using namespace nvcuda;

// Problem constants (fixed by the reference)
#define BATCH   2048
#define OBS_N   8
#define PRED_N  12
#define HID     512
#define G4      2048        /* 4*HID */
#define NSTEPS  19          /* (OBS-1) + PRED */
#define OBSTEPS 7           /* OBS-1 */
#define BH      (BATCH*HID)

// -------- scratch (device globals: allocation-free) --------
__device__ float g_X0[OBSTEPS * BH];        // embedded inputs, steps 0..6
__device__ float g_h[2 * BH];               // h per layer
__device__ float g_c[2 * BH];               // c per layer
__device__ float g_gates[BATCH * G4];       // gate pre-activations scratch
__device__ float g_vel[BATCH * PRED_N * 2]; // decoded velocities (raw predlist)

// -------- init h,c = 0 (graph replays must be deterministic) --------
__global__ void init_state_kernel() {
    int idx = blockIdx.x * blockDim.x + threadIdx.x;
    if (idx < 2 * BH) { g_h[idx] = 0.f; g_c[idx] = 0.f; }
}

// -------- embed: X0[t][b][j] = ((obsVel-mean)/std) @ enc_W + enc_b --------
__global__ void embed_kernel(const float* __restrict__ obsVel,
                             const float* __restrict__ mean,
                             const float* __restrict__ stdv,
                             const float* __restrict__ enc_W,
                             const float* __restrict__ enc_b) {
    int idx = blockIdx.x * blockDim.x + threadIdx.x;
    if (idx >= OBSTEPS * BH) return;
    int j  = idx % HID;
    int rb = idx / HID;
    int b  = rb % BATCH;
    int t  = rb / BATCH;
    float v0 = (obsVel[(b * OBS_N + t) * 2 + 0] - mean[0]) / stdv[0];
    float v1 = (obsVel[(b * OBS_N + t) * 2 + 1] - mean[1]) / stdv[1];
    g_X0[idx] = v0 * enc_W[j] + v1 * enc_W[HID + j] + enc_b[j];
}

// -------- gates GEMM: g_gates = X @ W1^T + Hprev @ W2^T (TF32 wmma) --------
// xIdx: 0..6 -> g_X0 step t ; 7 -> g_h (h0) ; 8 -> g_h+BH (h1)
#define BM 128
#define BN 128
#define BK 32
#define LDS (BK + 4)   /* 36, multiple of 4 for wmma ldm */

__global__ __launch_bounds__(256) void gemm_gates_kernel(
    const float* __restrict__ W1, const float* __restrict__ W2,
    int xIdx, int layer)
{
    __shared__ float As[BM][LDS];     // row-major (m,k)
    __shared__ float Bs[BN][LDS];     // col-major (k,n): elem(k,n) at Bs[n][k]

    const float* Xp = (xIdx < OBSTEPS) ? (g_X0 + (size_t)xIdx * BH)
                                       : (g_h + (size_t)(xIdx - OBSTEPS) * BH);
    const float* Hp = g_h + (size_t)layer * BH;

    const int m0 = blockIdx.y * BM;
    const int n0 = blockIdx.x * BN;
    const int tid = threadIdx.x;
    const int warp = tid >> 5;
    const int wr = warp >> 2;    // 0..1  (64-row strip)
    const int wc = warp & 3;     // 0..3  (32-col strip)

    wmma::fragment<wmma::accumulator, 16, 16, 8, float> acc[4][2];
    #pragma unroll
    for (int i = 0; i < 4; i++)
        #pragma unroll
        for (int j = 0; j < 2; j++)
            wmma::fill_fragment(acc[i][j], 0.0f);

    const int r  = tid >> 3;          // 0..31
    const int cg = (tid & 7) * 4;     // 0..28 step 4

    #pragma unroll 1
    for (int kb = 0; kb < (2 * HID) / BK; kb++) {   // 32 iters over K=1024
        const float* Ap; const float* Wp; int koff;
        if (kb < HID / BK) { Ap = Xp; Wp = W1; koff = kb * BK; }
        else               { Ap = Hp; Wp = W2; koff = (kb - HID / BK) * BK; }

        #pragma unroll
        for (int i = 0; i < 4; i++) {
            int row = r + i * 32;
            float4 va = *(const float4*)(Ap + (size_t)(m0 + row) * HID + koff + cg);
            As[row][cg + 0] = va.x; As[row][cg + 1] = va.y;
            As[row][cg + 2] = va.z; As[row][cg + 3] = va.w;
            float4 vb = *(const float4*)(Wp + (size_t)(n0 + row) * HID + koff + cg);
            Bs[row][cg + 0] = vb.x; Bs[row][cg + 1] = vb.y;
            Bs[row][cg + 2] = vb.z; Bs[row][cg + 3] = vb.w;
        }
        __syncthreads();

        #pragma unroll
        for (int ks = 0; ks < BK / 8; ks++) {
            wmma::fragment<wmma::matrix_a, 16, 16, 8, wmma::precision::tf32, wmma::row_major> fa[4];
            wmma::fragment<wmma::matrix_b, 16, 16, 8, wmma::precision::tf32, wmma::col_major> fb[2];
            #pragma unroll
            for (int i = 0; i < 4; i++) {
                wmma::load_matrix_sync(fa[i], &As[wr * 64 + i * 16][ks * 8], LDS);
                #pragma unroll
                for (int e = 0; e < fa[i].num_elements; e++)
                    fa[i].x[e] = wmma::__float_to_tf32(fa[i].x[e]);
            }
            #pragma unroll
            for (int j = 0; j < 2; j++) {
                wmma::load_matrix_sync(fb[j], &Bs[wc * 32 + j * 16][ks * 8], LDS);
                #pragma unroll
                for (int e = 0; e < fb[j].num_elements; e++)
                    fb[j].x[e] = wmma::__float_to_tf32(fb[j].x[e]);
            }
            #pragma unroll
            for (int i = 0; i < 4; i++)
                #pragma unroll
                for (int j = 0; j < 2; j++)
                    wmma::mma_sync(acc[i][j], fa[i], fb[j], acc[i][j]);
        }
        __syncthreads();
    }

    #pragma unroll
    for (int i = 0; i < 4; i++)
        #pragma unroll
        for (int j = 0; j < 2; j++)
            wmma::store_matrix_sync(
                &g_gates[(size_t)(m0 + wr * 64 + i * 16) * G4 + n0 + wc * 32 + j * 16],
                acc[i][j], G4, wmma::mem_row_major);
}

// -------- LSTM cell elementwise (adds biases, updates h,c in place) --------
__global__ void lstm_cell_kernel(const float* __restrict__ bih,
                                 const float* __restrict__ bhh,
                                 int layer) {
    int idx = blockIdx.x * blockDim.x + threadIdx.x;
    if (idx >= BH) return;
    int b = idx / HID, j = idx % HID;
    const float* gb = g_gates + (size_t)b * G4;
    const float* bi = bih + (size_t)layer * G4;
    const float* bh = bhh + (size_t)layer * G4;
    float gi = gb[j            ] + bi[j            ] + bh[j            ];
    float gf = gb[j +     HID  ] + bi[j +     HID  ] + bh[j +     HID  ];
    float gg = gb[j + 2 * HID  ] + bi[j + 2 * HID  ] + bh[j + 2 * HID  ];
    float go = gb[j + 3 * HID  ] + bi[j + 3 * HID  ] + bh[j + 3 * HID  ];
    float si = 1.0f / (1.0f + expf(-gi));
    float sf = 1.0f / (1.0f + expf(-gf));
    float so = 1.0f / (1.0f + expf(-go));
    float* cp = g_c + (size_t)layer * BH + idx;
    float* hp = g_h + (size_t)layer * BH + idx;
    float cn = sf * (*cp) + si * tanhf(gg);
    *cp = cn;
    *hp = so * tanhf(cn);
}

// -------- decoder: vel[b][k][:] = h1[b] @ dec_W + dec_b (one warp per b) ---
__global__ void decode_kernel(const float* __restrict__ dec_W,
                              const float* __restrict__ dec_b, int k) {
    int gwarp = (blockIdx.x * blockDim.x + threadIdx.x) >> 5;
    int lane = threadIdx.x & 31;
    if (gwarp >= BATCH) return;
    const float* h1 = g_h + BH + (size_t)gwarp * HID;
    float a0 = 0.f, a1 = 0.f;
    #pragma unroll
    for (int j = lane; j < HID; j += 32) {
        float hv = h1[j];
        a0 += hv * dec_W[2 * j];
        a1 += hv * dec_W[2 * j + 1];
    }
    #pragma unroll
    for (int off = 16; off > 0; off >>= 1) {
        a0 += __shfl_down_sync(0xffffffffu, a0, off);
        a1 += __shfl_down_sync(0xffffffffu, a1, off);
    }
    if (lane == 0) {
        g_vel[(gwarp * PRED_N + k) * 2 + 0] = a0 + dec_b[0];
        g_vel[(gwarp * PRED_N + k) * 2 + 1] = a1 + dec_b[1];
    }
}

// -------- finalize: pred = cumsum(vel*std+mean)+obs[:,-1,:]; write outputs -
__global__ void finalize_kernel(const float* __restrict__ obs,
                                const float* __restrict__ mean,
                                const float* __restrict__ stdv,
                                float* __restrict__ out, int out_size) {
    int i = blockIdx.x * blockDim.x + threadIdx.x;
    if (i >= BATCH * 2) return;
    int b = i >> 1, d = i & 1;
    float acc = obs[(b * OBS_N + (OBS_N - 1)) * 2 + d];
    float s = stdv[d], m = mean[d];
    const int VOFF = BATCH * PRED_N * 2;
    bool write_vel = (out_size >= 2 * VOFF);
    #pragma unroll
    for (int k = 0; k < PRED_N; k++) {
        float v = g_vel[(b * PRED_N + k) * 2 + d];
        acc += v * s + m;
        out[(b * PRED_N + k) * 2 + d] = acc;                 // pred
        if (write_vel) out[VOFF + (b * PRED_N + k) * 2 + d] = v;  // outVelocity
    }
}

extern "C" void kernel_launch(void* const* d_in, const int* in_sizes, int n_in,
                              void* d_out, int out_size) {
    const float* obs    = (const float*)d_in[0];
    const float* obsVel = (const float*)d_in[1];
    const float* mean   = (const float*)d_in[2];
    const float* stdv   = (const float*)d_in[3];
    const float* enc_W  = (const float*)d_in[4];
    const float* enc_b  = (const float*)d_in[5];
    const float* dec_W  = (const float*)d_in[6];
    const float* dec_b  = (const float*)d_in[7];
    const float* Wih    = (const float*)d_in[8];
    const float* Whh    = (const float*)d_in[9];
    const float* bih    = (const float*)d_in[10];
    const float* bhh    = (const float*)d_in[11];

    init_state_kernel<<<(2 * BH + 255) / 256, 256>>>();
    embed_kernel<<<(OBSTEPS * BH + 255) / 256, 256>>>(obsVel, mean, stdv, enc_W, enc_b);

    dim3 gg(G4 / BN, BATCH / BM);   // 16 x 16 tiles
    const size_t WSTRIDE = (size_t)G4 * HID;   // per-layer weight stride

    for (int t = 0; t < NSTEPS; t++) {
        // layer 0: x = embed[t] for obs phase, h1 (feedback) for pred phase
        int xIdx0 = (t < OBSTEPS) ? t : (OBSTEPS + 1);
        gemm_gates_kernel<<<gg, 256>>>(Wih, Whh, xIdx0, 0);
        lstm_cell_kernel<<<(BH + 255) / 256, 256>>>(bih, bhh, 0);
        // layer 1: x = freshly updated h0
        gemm_gates_kernel<<<gg, 256>>>(Wih + WSTRIDE, Whh + WSTRIDE, OBSTEPS, 1);
        lstm_cell_kernel<<<(BH + 255) / 256, 256>>>(bih, bhh, 1);
        // decode only the prediction-phase outputs
        if (t >= OBSTEPS)
            decode_kernel<<<(BATCH * 32 + 255) / 256, 256>>>(dec_W, dec_b, t - OBSTEPS);
    }

    finalize_kernel<<<(BATCH * 2 + 255) / 256, 256>>>(obs, mean, stdv,
                                                      (float*)d_out, out_size);
}

// round 2
// speedup vs baseline: 1.1794x; 1.1794x over previous
#include <cuda_runtime.h>
#include <mma.h>
#include <cstdint>
#include <cstddef>

using namespace nvcuda;

#define BATCH   2048
#define OBS_N   8
#define PRED_N  12
#define HID     512
#define G4      2048
#define NSTEPS  19
#define OBSTEPS 7
#define BH      (BATCH*HID)

// ---------------- scratch (device globals) ----------------
__device__ float g_X0[OBSTEPS * BH];          // embedded inputs t=0..6
__device__ float g_H[4 * BH];                 // [buf(2)][layer(2)][B][H] ping-pong
__device__ float g_c[2 * BH];                 // [layer][B][H] (in-place)
__device__ float g_Wp[2 * G4 * 1024];         // permuted+packed weights [l][r=4j+g][k:1024 = Wih|Whh]
__device__ float g_bias[2 * G4];              // permuted bih+bhh
__device__ float g_vel[BATCH * PRED_N * 2];

// ---------------- helpers ----------------
__device__ __forceinline__ void cp_async16(void* smem, const void* gptr) {
    uint32_t s = (uint32_t)__cvta_generic_to_shared(smem);
    asm volatile("cp.async.cg.shared.global [%0], [%1], 16;\n" :: "r"(s), "l"(gptr));
}
__device__ __forceinline__ void cp_commit() {
    asm volatile("cp.async.commit_group;\n");
}
template<int N> __device__ __forceinline__ void cp_wait() {
    asm volatile("cp.async.wait_group %0;\n" :: "n"(N));
}

// ---------------- init / embed ----------------
__global__ void init_state_kernel() {
    int idx = blockIdx.x * blockDim.x + threadIdx.x;
    if (idx < 2 * BH) {
        g_H[2 * BH + idx] = 0.f;   // buf 1 (read at step 0), both layers
        g_c[idx] = 0.f;
    }
}

__global__ void embed_kernel(const float* __restrict__ obsVel,
                             const float* __restrict__ mean,
                             const float* __restrict__ stdv,
                             const float* __restrict__ enc_W,
                             const float* __restrict__ enc_b) {
    int idx = blockIdx.x * blockDim.x + threadIdx.x;
    if (idx >= OBSTEPS * BH) return;
    int j  = idx % HID;
    int rb = idx / HID;
    int b  = rb % BATCH;
    int t  = rb / BATCH;
    float v0 = (obsVel[(b * OBS_N + t) * 2 + 0] - mean[0]) / stdv[0];
    float v1 = (obsVel[(b * OBS_N + t) * 2 + 1] - mean[1]) / stdv[1];
    g_X0[idx] = v0 * enc_W[j] + v1 * enc_W[HID + j] + enc_b[j];
}

// ---------------- one-time weight permute (gate-interleave + pack X|H) ------
// new row r = 4*j + g  <-  old row g*512 + j ; cols [0,512)=Wih, [512,1024)=Whh
__global__ void permute_w_kernel(const float* __restrict__ Wih,
                                 const float* __restrict__ Whh) {
    int i = blockIdx.x * blockDim.x + threadIdx.x;     // float4 index
    if (i >= 2 * G4 * 256) return;                     // 2*2048*1024/4
    int k4 = i & 255;
    int r  = (i >> 8) & 2047;
    int l  = i >> 19;
    int k  = k4 * 4;
    int g = r & 3, j = r >> 2;
    int oldrow = l * G4 + g * HID + j;
    const float* src = (k < HID) ? (Wih + (size_t)oldrow * HID + k)
                                 : (Whh + (size_t)oldrow * HID + (k - HID));
    ((float4*)g_Wp)[i] = *(const float4*)src;
}

__global__ void permute_b_kernel(const float* __restrict__ bih,
                                 const float* __restrict__ bhh) {
    int idx = blockIdx.x * blockDim.x + threadIdx.x;
    if (idx >= 2 * G4) return;
    int l = idx >> 11, r = idx & 2047;
    int g = r & 3, j = r >> 2;
    int old = l * G4 + g * HID + j;
    g_bias[idx] = bih[old] + bhh[old];
}

// ---------------- fused GEMM + LSTM cell ----------------
// gates = [X | Hprev] @ Wp^T ; epilogue applies cell, writes h_out, c.
// xsel: 0..6 -> g_X0[t] ; 7 -> h1 of previous step (buf wbuf^1) ; 8 -> h0 of
// current step (buf wbuf, written by the preceding layer-0 launch).
#define BM 128
#define BN 128
#define BK 32
#define LDS 36
#define NKB 32   /* K=1024 / BK */

__global__ __launch_bounds__(256, 2) void gemm_lstm_kernel(int xsel, int wbuf, int layer)
{
    extern __shared__ float smem[];
    float* As = smem;                     // [2][128][36]
    float* Bs = smem + 2 * BM * LDS;      // [2][128][36]

    const float* Xp;
    if (xsel < OBSTEPS)      Xp = g_X0 + (size_t)xsel * BH;
    else if (xsel == 7)      Xp = g_H + (size_t)((wbuf ^ 1) * 2 + 1) * BH;
    else                     Xp = g_H + (size_t)(wbuf * 2 + 0) * BH;
    const float* Hp   = g_H + (size_t)((wbuf ^ 1) * 2 + layer) * BH;
    float*       hout = g_H + (size_t)(wbuf * 2 + layer) * BH;
    float*       cst  = g_c + (size_t)layer * BH;
    const float* Wp   = g_Wp + (size_t)layer * G4 * 1024;
    const float* bias = g_bias + (size_t)layer * G4;

    const int m0 = blockIdx.y * BM;
    const int n0 = blockIdx.x * BN;
    const int tid = threadIdx.x;
    const int warp = tid >> 5;
    const int wr = warp >> 2;
    const int wc = warp & 3;
    const int lrow = tid >> 3;          // 0..31
    const int lcg  = (tid & 7) * 4;     // 0..28

    wmma::fragment<wmma::accumulator, 16, 16, 8, float> acc[4][2];
    #pragma unroll
    for (int i = 0; i < 4; i++)
        #pragma unroll
        for (int j = 0; j < 2; j++)
            wmma::fill_fragment(acc[i][j], 0.0f);

    // ---- stage loader ----
    auto load_stage = [&](int kb, int s) {
        const float* Ap = (kb < 16) ? Xp : Hp;
        int koff = (kb & 15) * BK;
        float* as = As + s * BM * LDS;
        float* bs = Bs + s * BM * LDS;
        #pragma unroll
        for (int i = 0; i < 4; i++) {
            int r = lrow + i * 32;
            cp_async16(&as[r * LDS + lcg], Ap + (size_t)(m0 + r) * HID + koff + lcg);
            cp_async16(&bs[r * LDS + lcg], Wp + (size_t)(n0 + r) * 1024 + kb * BK + lcg);
        }
        cp_commit();
    };

    load_stage(0, 0);

    #pragma unroll 1
    for (int kb = 0; kb < NKB; kb++) {
        int s = kb & 1;
        if (kb + 1 < NKB) { load_stage(kb + 1, s ^ 1); cp_wait<1>(); }
        else              { cp_wait<0>(); }
        __syncthreads();

        const float* as = As + s * BM * LDS;
        const float* bs = Bs + s * BM * LDS;
        #pragma unroll
        for (int ks = 0; ks < BK / 8; ks++) {
            wmma::fragment<wmma::matrix_a, 16, 16, 8, wmma::precision::tf32, wmma::row_major> fa[4];
            wmma::fragment<wmma::matrix_b, 16, 16, 8, wmma::precision::tf32, wmma::col_major> fb[2];
            #pragma unroll
            for (int i = 0; i < 4; i++) {
                wmma::load_matrix_sync(fa[i], &as[(wr * 64 + i * 16) * LDS + ks * 8], LDS);
                #pragma unroll
                for (int e = 0; e < fa[i].num_elements; e++)
                    fa[i].x[e] = wmma::__float_to_tf32(fa[i].x[e]);
            }
            #pragma unroll
            for (int j = 0; j < 2; j++) {
                wmma::load_matrix_sync(fb[j], &bs[(wc * 32 + j * 16) * LDS + ks * 8], LDS);
                #pragma unroll
                for (int e = 0; e < fb[j].num_elements; e++)
                    fb[j].x[e] = wmma::__float_to_tf32(fb[j].x[e]);
            }
            #pragma unroll
            for (int i = 0; i < 4; i++)
                #pragma unroll
                for (int j = 0; j < 2; j++)
                    wmma::mma_sync(acc[i][j], fa[i], fb[j], acc[i][j]);
        }
        __syncthreads();
    }

    // ---- epilogue: park gates in smem, apply LSTM cell ----
    float* Cs = smem;   // [128][128], 64KB (fits in 72KB dyn smem)
    #pragma unroll
    for (int i = 0; i < 4; i++)
        #pragma unroll
        for (int j = 0; j < 2; j++)
            wmma::store_matrix_sync(&Cs[(wr * 64 + i * 16) * BN + wc * 32 + j * 16],
                                    acc[i][j], BN, wmma::mem_row_major);
    __syncthreads();

    const int j0 = n0 >> 2;   // first hidden unit covered by this tile
    #pragma unroll
    for (int it = 0; it < 16; it++) {
        int idx = tid + it * 256;        // 0..4095 over (128 rows x 32 units)
        int bl = idx >> 5, jl = idx & 31;
        float4 gq = *(const float4*)&Cs[bl * BN + jl * 4];
        int rb = n0 + jl * 4;
        float gi = gq.x + bias[rb + 0];
        float gf = gq.y + bias[rb + 1];
        float gg = gq.z + bias[rb + 2];
        float go = gq.w + bias[rb + 3];
        float si = 1.0f / (1.0f + __expf(-gi));
        float sf = 1.0f / (1.0f + __expf(-gf));
        float so = 1.0f / (1.0f + __expf(-go));
        size_t ci = (size_t)(m0 + bl) * HID + j0 + jl;
        float cn = sf * cst[ci] + si * tanhf(gg);
        cst[ci]  = cn;
        hout[ci] = so * tanhf(cn);
    }
}

// ---------------- decoder ----------------
__global__ void decode_kernel(const float* __restrict__ dec_W,
                              const float* __restrict__ dec_b, int k, int wbuf) {
    int gwarp = (blockIdx.x * blockDim.x + threadIdx.x) >> 5;
    int lane = threadIdx.x & 31;
    if (gwarp >= BATCH) return;
    const float* h1 = g_H + (size_t)(wbuf * 2 + 1) * BH + (size_t)gwarp * HID;
    float a0 = 0.f, a1 = 0.f;
    #pragma unroll
    for (int j = lane; j < HID; j += 32) {
        float hv = h1[j];
        a0 += hv * dec_W[2 * j];
        a1 += hv * dec_W[2 * j + 1];
    }
    #pragma unroll
    for (int off = 16; off > 0; off >>= 1) {
        a0 += __shfl_down_sync(0xffffffffu, a0, off);
        a1 += __shfl_down_sync(0xffffffffu, a1, off);
    }
    if (lane == 0) {
        g_vel[(gwarp * PRED_N + k) * 2 + 0] = a0 + dec_b[0];
        g_vel[(gwarp * PRED_N + k) * 2 + 1] = a1 + dec_b[1];
    }
}

// ---------------- finalize ----------------
__global__ void finalize_kernel(const float* __restrict__ obs,
                                const float* __restrict__ mean,
                                const float* __restrict__ stdv,
                                float* __restrict__ out, int out_size) {
    int i = blockIdx.x * blockDim.x + threadIdx.x;
    if (i >= BATCH * 2) return;
    int b = i >> 1, d = i & 1;
    float acc = obs[(b * OBS_N + (OBS_N - 1)) * 2 + d];
    float s = stdv[d], m = mean[d];
    const int VOFF = BATCH * PRED_N * 2;
    bool write_vel = (out_size >= 2 * VOFF);
    #pragma unroll
    for (int k = 0; k < PRED_N; k++) {
        float v = g_vel[(b * PRED_N + k) * 2 + d];
        acc += v * s + m;
        out[(b * PRED_N + k) * 2 + d] = acc;
        if (write_vel) out[VOFF + (b * PRED_N + k) * 2 + d] = v;
    }
}

extern "C" void kernel_launch(void* const* d_in, const int* in_sizes, int n_in,
                              void* d_out, int out_size) {
    const float* obs    = (const float*)d_in[0];
    const float* obsVel = (const float*)d_in[1];
    const float* mean   = (const float*)d_in[2];
    const float* stdv   = (const float*)d_in[3];
    const float* enc_W  = (const float*)d_in[4];
    const float* enc_b  = (const float*)d_in[5];
    const float* dec_W  = (const float*)d_in[6];
    const float* dec_b  = (const float*)d_in[7];
    const float* Wih    = (const float*)d_in[8];
    const float* Whh    = (const float*)d_in[9];
    const float* bih    = (const float*)d_in[10];
    const float* bhh    = (const float*)d_in[11];

    const int SMEM = 4 * BM * LDS * (int)sizeof(float);   // 73728
    cudaFuncSetAttribute(gemm_lstm_kernel,
                         cudaFuncAttributeMaxDynamicSharedMemorySize, SMEM);

    init_state_kernel<<<(2 * BH + 255) / 256, 256>>>();
    embed_kernel<<<(OBSTEPS * BH + 255) / 256, 256>>>(obsVel, mean, stdv, enc_W, enc_b);
    permute_w_kernel<<<(2 * G4 * 256 + 255) / 256, 256>>>(Wih, Whh);
    permute_b_kernel<<<(2 * G4 + 255) / 256, 256>>>(bih, bhh);

    dim3 gg(G4 / BN, BATCH / BM);   // 16 x 16

    for (int t = 0; t < NSTEPS; t++) {
        int w = t & 1;
        int xsel0 = (t < OBSTEPS) ? t : 7;
        gemm_lstm_kernel<<<gg, 256, SMEM>>>(xsel0, w, 0);
        gemm_lstm_kernel<<<gg, 256, SMEM>>>(8, w, 1);
        if (t >= OBSTEPS)
            decode_kernel<<<(BATCH * 32 + 255) / 256, 256>>>(dec_W, dec_b, t - OBSTEPS, w);
    }

    finalize_kernel<<<(BATCH * 2 + 255) / 256, 256>>>(obs, mean, stdv,
                                                      (float*)d_out, out_size);
}

// round 4
// speedup vs baseline: 1.3346x; 1.1316x over previous
#include <cuda_runtime.h>
#include <mma.h>
#include <cstdint>
#include <cstddef>

using namespace nvcuda;

#define BATCH   2048
#define OBS_N   8
#define PRED_N  12
#define HID     512
#define G4      2048
#define NSTEPS  19
#define OBSTEPS 7
#define BH      (BATCH*HID)

// packed stage-image geometry: block = 128 rows x 36 floats (pad baked in)
#define RS      36
#define BLKF    4608          /* floats per block */
#define BLKB    18432u        /* bytes per block */
#define AIMGF   1179648       /* activation image: 16 mt x 16 kb blocks */
#define WIMGF   2359296       /* weight image per layer: 16 nt x 32 kb blocks */

// ---------------- scratch (device globals) ----------------
__device__ __align__(1024) float g_X0[OBSTEPS * AIMGF];
__device__ __align__(1024) float g_H[4 * AIMGF];      // [buf(2)][layer(2)] packed images
__device__ __align__(1024) float g_Wp[2 * WIMGF];     // packed weight images per layer
__device__ float g_c[2 * BH];                         // [layer][b][j] natural
__device__ float g_bias[2 * G4];                      // gate-interleaved bih+bhh
__device__ float g_vel[BATCH * PRED_N * 2];

// ---------------- helpers ----------------
__device__ __forceinline__ uint32_t smem_u32(const void* p) {
    uint32_t a;
    asm("{ .reg .u64 t; cvta.to.shared.u64 t, %1; cvt.u32.u64 %0, t; }" : "=r"(a) : "l"(p));
    return a;
}
__device__ __forceinline__ float f2tf(float x) {
    uint32_t y; asm("cvt.rna.tf32.f32 %0, %1;" : "=r"(y) : "f"(x));
    return __uint_as_float(y);
}
#define MBARRIER_INIT(addr, cnt) \
    asm volatile("mbarrier.init.shared.b64 [%0], %1;" :: "r"(addr), "r"(cnt) : "memory")
#define MBARRIER_INVAL(addr) \
    asm volatile("mbarrier.inval.shared.b64 [%0];" :: "r"(addr) : "memory")
#define MBARRIER_EXPECT_TX(addr, bytes) \
    asm volatile("mbarrier.arrive.expect_tx.shared.b64 _, [%0], %1;" :: "r"(addr), "r"(bytes) : "memory")
#define MBARRIER_WAIT_PARITY(addr, ph) do {                                   \
    uint32_t _m = (addr), _p = (ph), _d;                                      \
    asm volatile("{\n\t.reg .pred p;\n\t"                                     \
        "mbarrier.try_wait.parity.acquire.cta.shared::cta.b64 p, [%1], %2;\n\t" \
        "selp.b32 %0, 1, 0, p;\n\t}"                                          \
        : "=r"(_d) : "r"(_m), "r"(_p) : "memory");                            \
    if (!_d) {                                                                \
        asm volatile("{\n\t.reg .pred P1;\n\t"                                \
            "WL_%=:\n\t"                                                      \
            "mbarrier.try_wait.parity.acquire.cta.shared::cta.b64 P1, [%0], %1, 0x989680;\n\t" \
            "@P1 bra.uni WD_%=;\n\tbra.uni WL_%=;\n\tWD_%=:\n\t}"             \
            :: "r"(_m), "r"(_p) : "memory");                                  \
    }                                                                         \
} while (0)

__device__ __forceinline__ void bulk_g2s(uint32_t smem, const void* g,
                                         uint32_t bytes, uint32_t mbar) {
    asm volatile(
        "cp.async.bulk.shared::cta.global.mbarrier::complete_tx::bytes [%0], [%1], %2, [%3];"
        :: "r"(smem), "l"(g), "r"(bytes), "r"(mbar) : "memory");
}

// ---------------- init / embed / permute ----------------
__global__ void init_state_kernel() {
    int idx = blockIdx.x * blockDim.x + threadIdx.x;
    if (idx < 2 * AIMGF) g_H[2 * AIMGF + idx] = 0.f;   // buf 1, both layers
    if (idx < 2 * BH)    g_c[idx] = 0.f;
}

// packed + tf32-rounded X0 images
__global__ void embed_kernel(const float* __restrict__ obsVel,
                             const float* __restrict__ mean,
                             const float* __restrict__ stdv,
                             const float* __restrict__ enc_W,
                             const float* __restrict__ enc_b) {
    int idx = blockIdx.x * blockDim.x + threadIdx.x;
    if (idx >= OBSTEPS * BH) return;
    int j  = idx % HID;
    int rb = idx / HID;
    int b  = rb % BATCH;
    int t  = rb / BATCH;
    float v0 = (obsVel[(b * OBS_N + t) * 2 + 0] - mean[0]) / stdv[0];
    float v1 = (obsVel[(b * OBS_N + t) * 2 + 1] - mean[1]) / stdv[1];
    float v = v0 * enc_W[j] + v1 * enc_W[HID + j] + enc_b[j];
    int mt = b >> 7, row = b & 127, kb = j >> 5, kk = j & 31;
    g_X0[(size_t)t * AIMGF + (size_t)(mt * 16 + kb) * BLKF + row * RS + kk] = f2tf(v);
}

// weight image: [layer][nt(16)][kb(32)] blocks of [128 rows x 36]
// permuted row r = 4*j + g  <-  old row g*512 + j; cols k: [0,512)=Wih, [512,1024)=Whh
__global__ void permute_w_kernel(const float* __restrict__ Wih,
                                 const float* __restrict__ Whh) {
    int i = blockIdx.x * blockDim.x + threadIdx.x;     // float4 index
    if (i >= 2 * G4 * 256) return;
    int k4 = i & 255;
    int r  = (i >> 8) & 2047;
    int l  = i >> 19;
    int k  = k4 * 4;
    int g = r & 3, j = r >> 2;
    int oldrow = l * G4 + g * HID + j;
    const float* src = (k < HID) ? (Wih + (size_t)oldrow * HID + k)
                                 : (Whh + (size_t)oldrow * HID + (k - HID));
    float4 v = *(const float4*)src;
    v.x = f2tf(v.x); v.y = f2tf(v.y); v.z = f2tf(v.z); v.w = f2tf(v.w);
    int nt = r >> 7, rn = r & 127, kb = k >> 5, kk = k & 31;
    float* dst = g_Wp + (size_t)l * WIMGF + (size_t)(nt * 32 + kb) * BLKF + rn * RS + kk;
    *(float4*)dst = v;
}

__global__ void permute_b_kernel(const float* __restrict__ bih,
                                 const float* __restrict__ bhh) {
    int idx = blockIdx.x * blockDim.x + threadIdx.x;
    if (idx >= 2 * G4) return;
    int l = idx >> 11, r = idx & 2047;
    int g = r & 3, j = r >> 2;
    int old = l * G4 + g * HID + j;
    g_bias[idx] = bih[old] + bhh[old];
}

// ---------------- fused GEMM + LSTM cell (wmma tf32, bulk-fed) ----------------
#define BM 128
#define BN 128
#define BK 32
#define NKB 32
#define NSTG 3
#define STGB (2u * BLKB)            /* 36864 bytes per stage (A block + B block) */
#define SMEM_BYTES (1024 + NSTG * (int)STGB)

__global__ __launch_bounds__(256, 2) void gemm_lstm_kernel(int xsel, int wbuf, int layer)
{
    extern __shared__ char smem[];
    const uint32_t sb = smem_u32(smem);
    const uint32_t mb_full = sb + 16;           // NSTG x 8B
    const uint32_t stg0 = sb + 1024;

    const int tid = threadIdx.x;
    const int warp = tid >> 5;
    const int wr = warp >> 2;
    const int wc = warp & 3;
    const int nt = blockIdx.x;      // 0..15
    const int mt = blockIdx.y;      // 0..15
    const int n0 = nt * BN;

    // operand images
    const char* Xb;
    if (xsel < OBSTEPS)      Xb = (const char*)(g_X0 + (size_t)xsel * AIMGF);
    else if (xsel == 7)      Xb = (const char*)(g_H + (size_t)((wbuf ^ 1) * 2 + 1) * AIMGF);
    else                     Xb = (const char*)(g_H + (size_t)(wbuf * 2 + 0) * AIMGF);
    const char* Hb  = (const char*)(g_H + (size_t)((wbuf ^ 1) * 2 + layer) * AIMGF);
    float*     Hout = g_H + (size_t)(wbuf * 2 + layer) * AIMGF;
    const char* Wb  = (const char*)(g_Wp + (size_t)layer * WIMGF);
    float*      cst = g_c + (size_t)layer * BH;
    const float* bias = g_bias + (size_t)layer * G4;

    if (tid == 0) {
        #pragma unroll
        for (int s = 0; s < NSTG; s++) MBARRIER_INIT(mb_full + s * 8, 1);
    }
    __syncthreads();

    auto issue = [&](int kb) {
        int s = kb % NSTG;
        uint32_t st = stg0 + s * STGB;
        const char* asrc = ((kb < 16) ? Xb : Hb) + (size_t)(mt * 16 + (kb & 15)) * BLKB;
        const char* bsrc = Wb + (size_t)(nt * 32 + kb) * BLKB;
        MBARRIER_EXPECT_TX(mb_full + s * 8, STGB);
        bulk_g2s(st,        asrc, BLKB, mb_full + s * 8);
        bulk_g2s(st + BLKB, bsrc, BLKB, mb_full + s * 8);
    };

    if (tid == 0) { issue(0); issue(1); }

    wmma::fragment<wmma::accumulator, 16, 16, 8, float> acc[4][2];
    #pragma unroll
    for (int i = 0; i < 4; i++)
        #pragma unroll
        for (int j = 0; j < 2; j++)
            wmma::fill_fragment(acc[i][j], 0.0f);

    #pragma unroll 1
    for (int kb = 0; kb < NKB; kb++) {
        int s = kb % NSTG;
        __syncthreads();                       // stage (kb+2)%NSTG is now free
        if (tid == 0 && kb + 2 < NKB) issue(kb + 2);
        MBARRIER_WAIT_PARITY(mb_full + s * 8, (kb / NSTG) & 1);

        const float* as = (const float*)(smem + 1024 + (size_t)s * STGB);
        const float* bs = as + BLKF;
        #pragma unroll
        for (int ks = 0; ks < BK / 8; ks++) {
            wmma::fragment<wmma::matrix_a, 16, 16, 8, wmma::precision::tf32, wmma::row_major> fa[4];
            wmma::fragment<wmma::matrix_b, 16, 16, 8, wmma::precision::tf32, wmma::col_major> fb[2];
            #pragma unroll
            for (int i = 0; i < 4; i++)
                wmma::load_matrix_sync(fa[i], &as[(wr * 64 + i * 16) * RS + ks * 8], RS);
            #pragma unroll
            for (int j = 0; j < 2; j++)
                wmma::load_matrix_sync(fb[j], &bs[(wc * 32 + j * 16) * RS + ks * 8], RS);
            #pragma unroll
            for (int i = 0; i < 4; i++)
                #pragma unroll
                for (int j = 0; j < 2; j++)
                    wmma::mma_sync(acc[i][j], fa[i], fb[j], acc[i][j]);
        }
    }
    __syncthreads();

    // ---- epilogue: park gates in smem, apply LSTM cell, write packed h ----
    float* Cs = (float*)(smem + 1024);    // 64KB, fits in stage area
    #pragma unroll
    for (int i = 0; i < 4; i++)
        #pragma unroll
        for (int j = 0; j < 2; j++)
            wmma::store_matrix_sync(&Cs[(wr * 64 + i * 16) * BN + wc * 32 + j * 16],
                                    acc[i][j], BN, wmma::mem_row_major);
    __syncthreads();

    const int j0 = nt * 32;                 // hidden units covered: j0..j0+31
    const size_t hblk = (size_t)(mt * 16 + nt * 32 / 32) * BLKF;  // kb = nt (j>>5 == nt)
    #pragma unroll
    for (int it = 0; it < 16; it++) {
        int idx = tid + it * 256;           // 0..4095 over (128 rows x 32 units)
        int bl = idx >> 5, jl = idx & 31;
        float4 gq = *(const float4*)&Cs[bl * BN + jl * 4];
        int rb = n0 + jl * 4;
        float gi = gq.x + bias[rb + 0];
        float gf = gq.y + bias[rb + 1];
        float gg = gq.z + bias[rb + 2];
        float go = gq.w + bias[rb + 3];
        float si = 1.0f / (1.0f + __expf(-gi));
        float sf = 1.0f / (1.0f + __expf(-gf));
        float so = 1.0f / (1.0f + __expf(-go));
        size_t ci = (size_t)(mt * 128 + bl) * HID + j0 + jl;
        float cn = sf * cst[ci] + si * tanhf(gg);
        cst[ci] = cn;
        float hv = so * tanhf(cn);
        Hout[hblk + bl * RS + jl] = f2tf(hv);
    }

    __syncthreads();
    if (tid == 0) {
        #pragma unroll
        for (int s = 0; s < NSTG; s++) MBARRIER_INVAL(mb_full + s * 8);
    }
}

// ---------------- decoder (reads packed h1) ----------------
__global__ void decode_kernel(const float* __restrict__ dec_W,
                              const float* __restrict__ dec_b, int k, int wbuf) {
    int gwarp = (blockIdx.x * blockDim.x + threadIdx.x) >> 5;
    int lane = threadIdx.x & 31;
    if (gwarp >= BATCH) return;
    const float* h1 = g_H + (size_t)(wbuf * 2 + 1) * AIMGF;
    int mt = gwarp >> 7, row = gwarp & 127;
    float a0 = 0.f, a1 = 0.f;
    #pragma unroll
    for (int j = lane; j < HID; j += 32) {
        float hv = h1[(size_t)(mt * 16 + (j >> 5)) * BLKF + row * RS + (j & 31)];
        a0 += hv * dec_W[2 * j];
        a1 += hv * dec_W[2 * j + 1];
    }
    #pragma unroll
    for (int off = 16; off > 0; off >>= 1) {
        a0 += __shfl_down_sync(0xffffffffu, a0, off);
        a1 += __shfl_down_sync(0xffffffffu, a1, off);
    }
    if (lane == 0) {
        g_vel[(gwarp * PRED_N + k) * 2 + 0] = a0 + dec_b[0];
        g_vel[(gwarp * PRED_N + k) * 2 + 1] = a1 + dec_b[1];
    }
}

// ---------------- finalize ----------------
__global__ void finalize_kernel(const float* __restrict__ obs,
                                const float* __restrict__ mean,
                                const float* __restrict__ stdv,
                                float* __restrict__ out, int out_size) {
    int i = blockIdx.x * blockDim.x + threadIdx.x;
    if (i >= BATCH * 2) return;
    int b = i >> 1, d = i & 1;
    float acc = obs[(b * OBS_N + (OBS_N - 1)) * 2 + d];
    float s = stdv[d], m = mean[d];
    const int VOFF = BATCH * PRED_N * 2;
    bool write_vel = (out_size >= 2 * VOFF);
    #pragma unroll
    for (int k = 0; k < PRED_N; k++) {
        float v = g_vel[(b * PRED_N + k) * 2 + d];
        acc += v * s + m;
        out[(b * PRED_N + k) * 2 + d] = acc;
        if (write_vel) out[VOFF + (b * PRED_N + k) * 2 + d] = v;
    }
}

extern "C" void kernel_launch(void* const* d_in, const int* in_sizes, int n_in,
                              void* d_out, int out_size) {
    const float* obs    = (const float*)d_in[0];
    const float* obsVel = (const float*)d_in[1];
    const float* mean   = (const float*)d_in[2];
    const float* stdv   = (const float*)d_in[3];
    const float* enc_W  = (const float*)d_in[4];
    const float* enc_b  = (const float*)d_in[5];
    const float* dec_W  = (const float*)d_in[6];
    const float* dec_b  = (const float*)d_in[7];
    const float* Wih    = (const float*)d_in[8];
    const float* Whh    = (const float*)d_in[9];
    const float* bih    = (const float*)d_in[10];
    const float* bhh    = (const float*)d_in[11];

    cudaFuncSetAttribute(gemm_lstm_kernel,
                         cudaFuncAttributeMaxDynamicSharedMemorySize, SMEM_BYTES);

    init_state_kernel<<<(2 * AIMGF + 255) / 256, 256>>>();
    embed_kernel<<<(OBSTEPS * BH + 255) / 256, 256>>>(obsVel, mean, stdv, enc_W, enc_b);
    permute_w_kernel<<<(2 * G4 * 256 + 255) / 256, 256>>>(Wih, Whh);
    permute_b_kernel<<<(2 * G4 + 255) / 256, 256>>>(bih, bhh);

    dim3 gg(16, 16);   // nt x mt

    for (int t = 0; t < NSTEPS; t++) {
        int w = t & 1;
        int xsel0 = (t < OBSTEPS) ? t : 7;
        gemm_lstm_kernel<<<gg, 256, SMEM_BYTES>>>(xsel0, w, 0);
        gemm_lstm_kernel<<<gg, 256, SMEM_BYTES>>>(8, w, 1);
        if (t >= OBSTEPS)
            decode_kernel<<<(BATCH * 32 + 255) / 256, 256>>>(dec_W, dec_b, t - OBSTEPS, w);
    }

    finalize_kernel<<<(BATCH * 2 + 255) / 256, 256>>>(obs, mean, stdv,
                                                      (float*)d_out, out_size);
}

// round 6
// speedup vs baseline: 2.9373x; 2.2009x over previous
#include <cuda_runtime.h>
#include <cstdint>
#include <cstddef>

#define BATCH   2048
#define OBS_N   8
#define PRED_N  12
#define HID     512
#define G4      2048
#define NSTEPS  19
#define OBSTEPS 7
#define BH      (BATCH*HID)

// fragment-packed image geometry
#define ABLKF   4096                 /* A block: 128 rows x 32 k, fragment order */
#define ABLKB   16384u
#define AIMGF   (16*16*ABLKF)        /* 16 mt x 16 kb */
#define BBLKF   8192                 /* B block: 256 n-rows x 32 k */
#define BBLKB   32768u
#define WIMGF   (8*32*BBLKF)         /* 8 nt x 32 kb per layer */

// ---------------- scratch ----------------
__device__ __align__(1024) float g_X0[OBSTEPS * AIMGF];
__device__ __align__(1024) float g_H[4 * AIMGF];     // [buf(2)][layer(2)]
__device__ __align__(1024) float g_Wp[2 * WIMGF];
__device__ float g_c[2 * BH];
__device__ float g_bias[2 * G4];
__device__ float g_vel[BATCH * PRED_N * 2];

// ---------------- helpers ----------------
__device__ __forceinline__ uint32_t smem_u32(const void* p) {
    uint32_t a;
    asm("{ .reg .u64 t; cvta.to.shared.u64 t, %1; cvt.u32.u64 %0, t; }" : "=r"(a) : "l"(p));
    return a;
}
__device__ __forceinline__ float f2tf(float x) {
    uint32_t y; asm("cvt.rna.tf32.f32 %0, %1;" : "=r"(y) : "f"(x));
    return __uint_as_float(y);
}
// A fragment offset inside a 128x32 block (floats): mma m16n8k8 row-major A layout
__device__ __forceinline__ int a_off(int row, int jj) {
    int r = row & 15, c = jj & 7;
    int tile = ((jj >> 3) << 3) + (row >> 4);            // ki*8 + mi
    return tile * 128 + (((r & 7) << 2) + (c & 3)) * 4 + (r >> 3) + ((c >> 2) << 1);
}
// B fragment offset inside a 256x32 block (floats): mma m16n8k8 col B layout, k16-packed
__device__ __forceinline__ int b_off(int rn, int kk) {
    int tile = ((kk >> 4) << 5) + (rn >> 3);             // kpair*32 + ni
    int k16 = kk & 15;
    return tile * 128 + (((rn & 7) << 2) + (k16 & 3)) * 4 + (k16 >> 2);
}

#define MBARRIER_INIT(addr, cnt) \
    asm volatile("mbarrier.init.shared.b64 [%0], %1;" :: "r"(addr), "r"(cnt) : "memory")
#define MBARRIER_INVAL(addr) \
    asm volatile("mbarrier.inval.shared.b64 [%0];" :: "r"(addr) : "memory")
#define MBARRIER_EXPECT_TX(addr, bytes) \
    asm volatile("mbarrier.arrive.expect_tx.shared.b64 _, [%0], %1;" :: "r"(addr), "r"(bytes) : "memory")
#define MBARRIER_WAIT_PARITY(addr, ph) do {                                   \
    uint32_t _m = (addr), _p = (ph), _d;                                      \
    asm volatile("{\n\t.reg .pred p;\n\t"                                     \
        "mbarrier.try_wait.parity.acquire.cta.shared::cta.b64 p, [%1], %2;\n\t" \
        "selp.b32 %0, 1, 0, p;\n\t}"                                          \
        : "=r"(_d) : "r"(_m), "r"(_p) : "memory");                            \
    if (!_d) {                                                                \
        asm volatile("{\n\t.reg .pred P1;\n\t"                                \
            "WL_%=:\n\t"                                                      \
            "mbarrier.try_wait.parity.acquire.cta.shared::cta.b64 P1, [%0], %1, 0x989680;\n\t" \
            "@P1 bra.uni WD_%=;\n\tbra.uni WL_%=;\n\tWD_%=:\n\t}"             \
            :: "r"(_m), "r"(_p) : "memory");                                  \
    }                                                                         \
} while (0)

__device__ __forceinline__ void bulk_g2s(uint32_t smem, const void* g,
                                         uint32_t bytes, uint32_t mbar) {
    asm volatile(
        "cp.async.bulk.shared::cta.global.mbarrier::complete_tx::bytes [%0], [%1], %2, [%3];"
        :: "r"(smem), "l"(g), "r"(bytes), "r"(mbar) : "memory");
}

__device__ __forceinline__ void mma8(float* d, const float4& a, float b0, float b1) {
    asm volatile(
        "mma.sync.aligned.m16n8k8.row.col.f32.tf32.tf32.f32 "
        "{%0,%1,%2,%3},{%4,%5,%6,%7},{%8,%9},{%0,%1,%2,%3};"
        : "+f"(d[0]), "+f"(d[1]), "+f"(d[2]), "+f"(d[3])
        : "r"(__float_as_uint(a.x)), "r"(__float_as_uint(a.y)),
          "r"(__float_as_uint(a.z)), "r"(__float_as_uint(a.w)),
          "r"(__float_as_uint(b0)), "r"(__float_as_uint(b1)));
}

// ---------------- init / embed / permute ----------------
__global__ void init_state_kernel() {
    int idx = blockIdx.x * blockDim.x + threadIdx.x;
    if (idx < 2 * AIMGF) g_H[2 * AIMGF + idx] = 0.f;   // buf 1, both layers
    if (idx < 2 * BH)    g_c[idx] = 0.f;
}

__global__ void embed_kernel(const float* __restrict__ obsVel,
                             const float* __restrict__ mean,
                             const float* __restrict__ stdv,
                             const float* __restrict__ enc_W,
                             const float* __restrict__ enc_b) {
    int idx = blockIdx.x * blockDim.x + threadIdx.x;
    if (idx >= OBSTEPS * BH) return;
    int j  = idx % HID;
    int rb = idx / HID;
    int b  = rb % BATCH;
    int t  = rb / BATCH;
    float v0 = (obsVel[(b * OBS_N + t) * 2 + 0] - mean[0]) / stdv[0];
    float v1 = (obsVel[(b * OBS_N + t) * 2 + 1] - mean[1]) / stdv[1];
    float v = v0 * enc_W[j] + v1 * enc_W[HID + j] + enc_b[j];
    int mt = b >> 7, row = b & 127, kb = j >> 5;
    g_X0[(size_t)t * AIMGF + (size_t)(mt * 16 + kb) * ABLKF + a_off(row, j & 31)] = f2tf(v);
}

// weight image: permuted row r = 4*j + g; cols k: [0,512)=Wih, [512,1024)=Whh
__global__ void permute_w_kernel(const float* __restrict__ Wih,
                                 const float* __restrict__ Whh) {
    int i = blockIdx.x * blockDim.x + threadIdx.x;
    if (i >= 2 * G4 * 1024) return;
    int k = i & 1023;
    int r = (i >> 10) & 2047;
    int l = i >> 21;
    int g = r & 3, j = r >> 2;
    int oldrow = l * G4 + g * HID + j;
    float val = (k < HID) ? Wih[(size_t)oldrow * HID + k]
                          : Whh[(size_t)oldrow * HID + (k - HID)];
    int nt = r >> 8, rn = r & 255, kb = k >> 5, kk = k & 31;
    g_Wp[(size_t)l * WIMGF + (size_t)(nt * 32 + kb) * BBLKF + b_off(rn, kk)] = f2tf(val);
}

__global__ void permute_b_kernel(const float* __restrict__ bih,
                                 const float* __restrict__ bhh) {
    int idx = blockIdx.x * blockDim.x + threadIdx.x;
    if (idx >= 2 * G4) return;
    int l = idx >> 11, r = idx & 2047;
    int g = r & 3, j = r >> 2;
    int old = l * G4 + g * HID + j;
    g_bias[idx] = bih[old] + bhh[old];
}

// ---------------- fused GEMM + LSTM (raw mma, fragment-packed, bulk-fed) ----
#define NKB  32
#define NSTG 3
#define STGB (ABLKB + BBLKB)                  /* 49152 */
#define SMEM_BYTES (1024 + NSTG * (int)STGB)  /* 148480 */
#define CSTR 260                              /* skewed epilogue stride */

__global__ __launch_bounds__(256, 1) void gemm_lstm_kernel(int xsel, int wbuf, int layer)
{
    extern __shared__ char smem[];
    const uint32_t sb = smem_u32(smem);
    const uint32_t mb_full = sb + 16;
    const uint32_t stg0 = sb + 1024;

    const int tid = threadIdx.x;
    const int warp = tid >> 5;
    const int lane = tid & 31;
    const int wr = warp >> 2;       // 0..1  (m 64-strip)
    const int wc = warp & 3;        // 0..3  (n 64-strip)
    const int nt = blockIdx.x;      // 0..7   (256 gate-cols)
    const int mt = blockIdx.y;      // 0..15  (128 rows)

    const char* Xb;
    if (xsel < OBSTEPS)      Xb = (const char*)(g_X0 + (size_t)xsel * AIMGF);
    else if (xsel == 7)      Xb = (const char*)(g_H + (size_t)((wbuf ^ 1) * 2 + 1) * AIMGF);
    else                     Xb = (const char*)(g_H + (size_t)(wbuf * 2 + 0) * AIMGF);
    const char* Hb  = (const char*)(g_H + (size_t)((wbuf ^ 1) * 2 + layer) * AIMGF);
    float*     Hout = g_H + (size_t)(wbuf * 2 + layer) * AIMGF;
    const char* Wb  = (const char*)(g_Wp + (size_t)layer * WIMGF);
    float*      cst = g_c + (size_t)layer * BH;
    const float* bias = g_bias + (size_t)layer * G4;

    if (tid == 0) {
        #pragma unroll
        for (int s = 0; s < NSTG; s++) MBARRIER_INIT(mb_full + s * 8, 1);
    }
    __syncthreads();

    auto issue = [&](int kb) {
        int s = kb % NSTG;
        uint32_t st = stg0 + s * STGB;
        const char* asrc = ((kb < 16) ? Xb : Hb) + (size_t)(mt * 16 + (kb & 15)) * ABLKB;
        const char* bsrc = Wb + (size_t)(nt * 32 + kb) * BBLKB;
        MBARRIER_EXPECT_TX(mb_full + s * 8, STGB);
        bulk_g2s(st,         asrc, ABLKB, mb_full + s * 8);
        bulk_g2s(st + ABLKB, bsrc, BBLKB, mb_full + s * 8);
    };

    if (tid == 0) { issue(0); issue(1); }

    float acc[4][8][4];
    #pragma unroll
    for (int mi = 0; mi < 4; mi++)
        #pragma unroll
        for (int ni = 0; ni < 8; ni++)
            #pragma unroll
            for (int q = 0; q < 4; q++) acc[mi][ni][q] = 0.f;

    #pragma unroll 1
    for (int kb = 0; kb < NKB; kb++) {
        int s = kb % NSTG;
        __syncthreads();
        if (tid == 0 && kb + 2 < NKB) issue(kb + 2);
        MBARRIER_WAIT_PARITY(mb_full + s * 8, (kb / NSTG) & 1);

        const float4* as4 = (const float4*)(smem + 1024 + (size_t)s * STGB);
        const float4* bs4 = (const float4*)(smem + 1024 + (size_t)s * STGB + ABLKB);

        #pragma unroll
        for (int kp = 0; kp < 2; kp++) {
            float4 bf[8];
            #pragma unroll
            for (int ni = 0; ni < 8; ni++)
                bf[ni] = bs4[(kp * 32 + wc * 8 + ni) * 32 + lane];
            #pragma unroll
            for (int kh = 0; kh < 2; kh++) {
                int ki = kp * 2 + kh;
                float4 af[4];
                #pragma unroll
                for (int mi = 0; mi < 4; mi++)
                    af[mi] = as4[(ki * 8 + wr * 4 + mi) * 32 + lane];
                #pragma unroll
                for (int mi = 0; mi < 4; mi++)
                    #pragma unroll
                    for (int ni = 0; ni < 8; ni++) {
                        float b0 = kh ? bf[ni].z : bf[ni].x;
                        float b1 = kh ? bf[ni].w : bf[ni].y;
                        mma8(acc[mi][ni], af[mi], b0, b1);
                    }
            }
        }
    }
    __syncthreads();

    // ---- epilogue: gates -> skewed smem -> LSTM cell -> packed h ----
    float* Cs = (float*)(smem + 1024);
    #pragma unroll
    for (int mi = 0; mi < 4; mi++)
        #pragma unroll
        for (int ni = 0; ni < 8; ni++) {
            int row0 = wr * 64 + mi * 16 + (lane >> 2);
            int col  = wc * 64 + ni * 8 + (lane & 3) * 2;
            *(float2*)&Cs[row0 * CSTR + col]       = make_float2(acc[mi][ni][0], acc[mi][ni][1]);
            *(float2*)&Cs[(row0 + 8) * CSTR + col] = make_float2(acc[mi][ni][2], acc[mi][ni][3]);
        }
    __syncthreads();

    #pragma unroll
    for (int it = 0; it < 32; it++) {
        int idx = tid + it * 256;          // 128 rows x 64 units
        int bl = idx >> 6, jl = idx & 63;
        float4 gq = *(const float4*)&Cs[bl * CSTR + jl * 4];
        int rb = nt * 256 + jl * 4;
        float gi = gq.x + bias[rb + 0];
        float gf = gq.y + bias[rb + 1];
        float gg = gq.z + bias[rb + 2];
        float go = gq.w + bias[rb + 3];
        float si = 1.0f / (1.0f + __expf(-gi));
        float sf = 1.0f / (1.0f + __expf(-gf));
        float so = 1.0f / (1.0f + __expf(-go));
        int j = nt * 64 + jl;
        size_t ci = (size_t)(mt * 128 + bl) * HID + j;
        float cn = sf * cst[ci] + si * tanhf(gg);
        cst[ci] = cn;
        float hv = so * tanhf(cn);
        Hout[(size_t)(mt * 16 + (j >> 5)) * ABLKF + a_off(bl, j & 31)] = f2tf(hv);
    }

    __syncthreads();
    if (tid == 0) {
        #pragma unroll
        for (int s = 0; s < NSTG; s++) MBARRIER_INVAL(mb_full + s * 8);
    }
}

// ---------------- decoder (reads packed h1) ----------------
__global__ void decode_kernel(const float* __restrict__ dec_W,
                              const float* __restrict__ dec_b, int k, int wbuf) {
    int gwarp = (blockIdx.x * blockDim.x + threadIdx.x) >> 5;
    int lane = threadIdx.x & 31;
    if (gwarp >= BATCH) return;
    const float* h1 = g_H + (size_t)(wbuf * 2 + 1) * AIMGF;
    int mt = gwarp >> 7, row = gwarp & 127;
    float a0 = 0.f, a1 = 0.f;
    #pragma unroll
    for (int j = lane; j < HID; j += 32) {
        float hv = h1[(size_t)(mt * 16 + (j >> 5)) * ABLKF + a_off(row, j & 31)];
        a0 += hv * dec_W[2 * j];
        a1 += hv * dec_W[2 * j + 1];
    }
    #pragma unroll
    for (int off = 16; off > 0; off >>= 1) {
        a0 += __shfl_down_sync(0xffffffffu, a0, off);
        a1 += __shfl_down_sync(0xffffffffu, a1, off);
    }
    if (lane == 0) {
        g_vel[(gwarp * PRED_N + k) * 2 + 0] = a0 + dec_b[0];
        g_vel[(gwarp * PRED_N + k) * 2 + 1] = a1 + dec_b[1];
    }
}

// ---------------- finalize ----------------
__global__ void finalize_kernel(const float* __restrict__ obs,
                                const float* __restrict__ mean,
                                const float* __restrict__ stdv,
                                float* __restrict__ out, int out_size) {
    int i = blockIdx.x * blockDim.x + threadIdx.x;
    if (i >= BATCH * 2) return;
    int b = i >> 1, d = i & 1;
    float acc = obs[(b * OBS_N + (OBS_N - 1)) * 2 + d];
    float s = stdv[d], m = mean[d];
    const int VOFF = BATCH * PRED_N * 2;
    bool write_vel = (out_size >= 2 * VOFF);
    #pragma unroll
    for (int k = 0; k < PRED_N; k++) {
        float v = g_vel[(b * PRED_N + k) * 2 + d];
        acc += v * s + m;
        out[(b * PRED_N + k) * 2 + d] = acc;
        if (write_vel) out[VOFF + (b * PRED_N + k) * 2 + d] = v;
    }
}

extern "C" void kernel_launch(void* const* d_in, const int* in_sizes, int n_in,
                              void* d_out, int out_size) {
    const float* obs    = (const float*)d_in[0];
    const float* obsVel = (const float*)d_in[1];
    const float* mean   = (const float*)d_in[2];
    const float* stdv   = (const float*)d_in[3];
    const float* enc_W  = (const float*)d_in[4];
    const float* enc_b  = (const float*)d_in[5];
    const float* dec_W  = (const float*)d_in[6];
    const float* dec_b  = (const float*)d_in[7];
    const float* Wih    = (const float*)d_in[8];
    const float* Whh    = (const float*)d_in[9];
    const float* bih    = (const float*)d_in[10];
    const float* bhh    = (const float*)d_in[11];

    cudaFuncSetAttribute(gemm_lstm_kernel,
                         cudaFuncAttributeMaxDynamicSharedMemorySize, SMEM_BYTES);

    init_state_kernel<<<(2 * AIMGF + 255) / 256, 256>>>();
    embed_kernel<<<(OBSTEPS * BH + 255) / 256, 256>>>(obsVel, mean, stdv, enc_W, enc_b);
    permute_w_kernel<<<(2 * G4 * 1024 + 255) / 256, 256>>>(Wih, Whh);
    permute_b_kernel<<<(2 * G4 + 255) / 256, 256>>>(bih, bhh);

    dim3 gg(8, 16);    // nt x mt : 128 CTAs, one wave

    for (int t = 0; t < NSTEPS; t++) {
        int w = t & 1;
        int xsel0 = (t < OBSTEPS) ? t : 7;
        gemm_lstm_kernel<<<gg, 256, SMEM_BYTES>>>(xsel0, w, 0);
        gemm_lstm_kernel<<<gg, 256, SMEM_BYTES>>>(8, w, 1);
        if (t >= OBSTEPS)
            decode_kernel<<<(BATCH * 32 + 255) / 256, 256>>>(dec_W, dec_b, t - OBSTEPS, w);
    }

    finalize_kernel<<<(BATCH * 2 + 255) / 256, 256>>>(obs, mean, stdv,
                                                      (float*)d_out, out_size);
}

// round 8
// speedup vs baseline: 4.5790x; 1.5589x over previous
#include <cuda_runtime.h>
#include <cuda_fp16.h>
#include <cstdint>
#include <cstddef>

#define BATCH   2048
#define OBS_N   8
#define PRED_N  12
#define HID     512
#define G4      2048
#define NSTEPS  19
#define OBSTEPS 7
#define BH      (BATCH*HID)

// fp16 fragment-packed image geometry (BK = 64)
#define ABLKH   8192                 /* A block: 128 rows x 64 k halfs */
#define ABLKB   16384u
#define AIMGH   (16*8*ABLKH)         /* 16 mt x 8 kb blocks */
#define BBLKH   16384                /* B block: 256 n-rows x 64 k halfs */
#define BBLKB   32768u
#define WIMGH   (8*16*BBLKH)         /* 8 nt x 16 kb per layer */

// ---------------- scratch ----------------
__device__ __align__(1024) __half g_X0[OBSTEPS * AIMGH];
__device__ __align__(1024) __half g_H[4 * AIMGH];     // [buf(2)][layer(2)]
__device__ __align__(1024) __half g_Wp[2 * WIMGH];
__device__ float g_c[2 * BH];
__device__ float g_bias[2 * G4];
__device__ float g_vel[BATCH * PRED_N * 2];

// ---------------- helpers ----------------
__device__ __forceinline__ uint32_t smem_u32(const void* p) {
    uint32_t a;
    asm("{ .reg .u64 t; cvta.to.shared.u64 t, %1; cvt.u32.u64 %0, t; }" : "=r"(a) : "l"(p));
    return a;
}
// A (m16n8k16 row-major) half-index within a 128x64 block.
// tile = m16k16 tile (256 halfs = 1 uint4/lane), consumer reads as4[tile*32+lane].
__device__ __forceinline__ int a_off_h(int row, int k) {
    int mi = row >> 4, r = row & 15;
    int ki = k >> 4,  kk = k & 15;
    int tile = ki * 8 + mi;                        // 0..31
    int lane = (r & 7) * 4 + ((kk & 7) >> 1);
    int sel  = ((r >> 3) & 1) + ((kk >> 3) << 1);  // a0..a3 (b32 reg)
    return tile * 256 + lane * 8 + sel * 2 + (kk & 1);
}
// B (m16n8k16 col) half-index within a 256x64 block, k32-paired per uint4.
// tile = (kp, n8) group (256 halfs = 1 uint4/lane), consumer reads bs4[tile*32+lane].
__device__ __forceinline__ int b_off_h(int rn, int k) {
    int kp = k >> 5, k32 = k & 31;
    int ki_in = k32 >> 4, kk = k32 & 15;
    int tile = kp * 32 + (rn >> 3);                // 0..63
    int lane = (rn & 7) * 4 + ((kk & 7) >> 1);
    int sel  = ki_in * 2 + (kk >> 3);              // x,y,z,w
    return tile * 256 + lane * 8 + sel * 2 + (kk & 1);
}

#define MBARRIER_INIT(addr, cnt) \
    asm volatile("mbarrier.init.shared.b64 [%0], %1;" :: "r"(addr), "r"(cnt) : "memory")
#define MBARRIER_INVAL(addr) \
    asm volatile("mbarrier.inval.shared.b64 [%0];" :: "r"(addr) : "memory")
#define MBARRIER_EXPECT_TX(addr, bytes) \
    asm volatile("mbarrier.arrive.expect_tx.shared.b64 _, [%0], %1;" :: "r"(addr), "r"(bytes) : "memory")
#define MBARRIER_WAIT_PARITY(addr, ph) do {                                   \
    uint32_t _m = (addr), _p = (ph), _d;                                      \
    asm volatile("{\n\t.reg .pred p;\n\t"                                     \
        "mbarrier.try_wait.parity.acquire.cta.shared::cta.b64 p, [%1], %2;\n\t" \
        "selp.b32 %0, 1, 0, p;\n\t}"                                          \
        : "=r"(_d) : "r"(_m), "r"(_p) : "memory");                            \
    if (!_d) {                                                                \
        asm volatile("{\n\t.reg .pred P1;\n\t"                                \
            "WL_%=:\n\t"                                                      \
            "mbarrier.try_wait.parity.acquire.cta.shared::cta.b64 P1, [%0], %1, 0x989680;\n\t" \
            "@P1 bra.uni WD_%=;\n\tbra.uni WL_%=;\n\tWD_%=:\n\t}"             \
            :: "r"(_m), "r"(_p) : "memory");                                  \
    }                                                                         \
} while (0)

__device__ __forceinline__ void bulk_g2s(uint32_t smem, const void* g,
                                         uint32_t bytes, uint32_t mbar) {
    asm volatile(
        "cp.async.bulk.shared::cta.global.mbarrier::complete_tx::bytes [%0], [%1], %2, [%3];"
        :: "r"(smem), "l"(g), "r"(bytes), "r"(mbar) : "memory");
}

__device__ __forceinline__ void mma16(float* d, const uint4& a, uint32_t b0, uint32_t b1) {
    asm volatile(
        "mma.sync.aligned.m16n8k16.row.col.f32.f16.f16.f32 "
        "{%0,%1,%2,%3},{%4,%5,%6,%7},{%8,%9},{%0,%1,%2,%3};"
        : "+f"(d[0]), "+f"(d[1]), "+f"(d[2]), "+f"(d[3])
        : "r"(a.x), "r"(a.y), "r"(a.z), "r"(a.w), "r"(b0), "r"(b1));
}

// ---------------- init / embed / permute ----------------
__global__ void init_state_kernel() {
    int idx = blockIdx.x * blockDim.x + threadIdx.x;
    if (idx < 2 * AIMGH) g_H[2 * AIMGH + idx] = __float2half(0.f);
    if (idx < 2 * BH)    g_c[idx] = 0.f;
}

__global__ void embed_kernel(const float* __restrict__ obsVel,
                             const float* __restrict__ mean,
                             const float* __restrict__ stdv,
                             const float* __restrict__ enc_W,
                             const float* __restrict__ enc_b) {
    int idx = blockIdx.x * blockDim.x + threadIdx.x;
    if (idx >= OBSTEPS * BH) return;
    int j  = idx % HID;
    int rb = idx / HID;
    int b  = rb % BATCH;
    int t  = rb / BATCH;
    float v0 = (obsVel[(b * OBS_N + t) * 2 + 0] - mean[0]) / stdv[0];
    float v1 = (obsVel[(b * OBS_N + t) * 2 + 1] - mean[1]) / stdv[1];
    float v = v0 * enc_W[j] + v1 * enc_W[HID + j] + enc_b[j];
    int mt = b >> 7, row = b & 127;
    g_X0[(size_t)t * AIMGH + (size_t)(mt * 8 + (j >> 6)) * ABLKH + a_off_h(row, j & 63)]
        = __float2half_rn(v);
}

// weight image: permuted row r = 4*j + g; cols k: [0,512)=Wih, [512,1024)=Whh
__global__ void permute_w_kernel(const float* __restrict__ Wih,
                                 const float* __restrict__ Whh) {
    int i = blockIdx.x * blockDim.x + threadIdx.x;
    if (i >= 2 * G4 * 1024) return;
    int k = i & 1023;
    int r = (i >> 10) & 2047;
    int l = i >> 21;
    int g = r & 3, j = r >> 2;
    int oldrow = l * G4 + g * HID + j;
    float val = (k < HID) ? Wih[(size_t)oldrow * HID + k]
                          : Whh[(size_t)oldrow * HID + (k - HID)];
    int nt = r >> 8, rn = r & 255, kb = k >> 6;
    g_Wp[(size_t)l * WIMGH + (size_t)(nt * 16 + kb) * BBLKH + b_off_h(rn, k & 63)]
        = __float2half_rn(val);
}

__global__ void permute_b_kernel(const float* __restrict__ bih,
                                 const float* __restrict__ bhh) {
    int idx = blockIdx.x * blockDim.x + threadIdx.x;
    if (idx >= 2 * G4) return;
    int l = idx >> 11, r = idx & 2047;
    int g = r & 3, j = r >> 2;
    int old = l * G4 + g * HID + j;
    g_bias[idx] = bih[old] + bhh[old];
}

// ---------------- fused GEMM + LSTM (fp16 mma, fragment-packed, bulk-fed) ---
#define NKB  16
#define NSTG 3
#define STGB (ABLKB + BBLKB)                  /* 49152 */
#define SMEM_BYTES (1024 + NSTG * (int)STGB)  /* 148480 */
#define CSTR 260

__global__ __launch_bounds__(256, 1) void gemm_lstm_kernel(int xsel, int wbuf, int layer)
{
    extern __shared__ char smem[];
    const uint32_t sb = smem_u32(smem);
    const uint32_t mb_full = sb + 16;
    const uint32_t stg0 = sb + 1024;

    const int tid = threadIdx.x;
    const int warp = tid >> 5;
    const int lane = tid & 31;
    const int wr = warp >> 2;       // 0..1 (m 64-strip)
    const int wc = warp & 3;        // 0..3 (n 64-strip)
    const int nt = blockIdx.x;      // 0..7
    const int mt = blockIdx.y;      // 0..15

    const char* Xb;
    if (xsel < OBSTEPS)      Xb = (const char*)(g_X0 + (size_t)xsel * AIMGH);
    else if (xsel == 7)      Xb = (const char*)(g_H + (size_t)((wbuf ^ 1) * 2 + 1) * AIMGH);
    else                     Xb = (const char*)(g_H + (size_t)(wbuf * 2 + 0) * AIMGH);
    const char* Hb  = (const char*)(g_H + (size_t)((wbuf ^ 1) * 2 + layer) * AIMGH);
    __half*    Hout = g_H + (size_t)(wbuf * 2 + layer) * AIMGH;
    const char* Wb  = (const char*)(g_Wp + (size_t)layer * WIMGH);
    float*      cst = g_c + (size_t)layer * BH;
    const float* bias = g_bias + (size_t)layer * G4;

    if (tid == 0) {
        #pragma unroll
        for (int s = 0; s < NSTG; s++) MBARRIER_INIT(mb_full + s * 8, 1);
    }
    __syncthreads();

    auto issue = [&](int kb) {
        int s = kb % NSTG;
        uint32_t st = stg0 + s * STGB;
        const char* asrc = ((kb < 8) ? Xb : Hb) + (size_t)(mt * 8 + (kb & 7)) * ABLKB;
        const char* bsrc = Wb + (size_t)(nt * 16 + kb) * BBLKB;
        MBARRIER_EXPECT_TX(mb_full + s * 8, STGB);
        bulk_g2s(st,         asrc, ABLKB, mb_full + s * 8);
        bulk_g2s(st + ABLKB, bsrc, BBLKB, mb_full + s * 8);
    };

    if (tid == 0) { issue(0); issue(1); }

    float acc[4][8][4];
    #pragma unroll
    for (int mi = 0; mi < 4; mi++)
        #pragma unroll
        for (int ni = 0; ni < 8; ni++)
            #pragma unroll
            for (int q = 0; q < 4; q++) acc[mi][ni][q] = 0.f;

    #pragma unroll 1
    for (int kb = 0; kb < NKB; kb++) {
        int s = kb % NSTG;
        __syncthreads();
        if (tid == 0 && kb + 2 < NKB) issue(kb + 2);
        MBARRIER_WAIT_PARITY(mb_full + s * 8, (kb / NSTG) & 1);

        const uint4* as4 = (const uint4*)(smem + 1024 + (size_t)s * STGB);
        const uint4* bs4 = (const uint4*)(smem + 1024 + (size_t)s * STGB + ABLKB);

        #pragma unroll
        for (int kp = 0; kp < 2; kp++) {           // k32 pairs within BK=64
            uint4 bf[8];
            #pragma unroll
            for (int ni = 0; ni < 8; ni++)
                bf[ni] = bs4[(kp * 32 + wc * 8 + ni) * 32 + lane];
            #pragma unroll
            for (int kh = 0; kh < 2; kh++) {       // k16 within k32
                int ki = kp * 2 + kh;
                uint4 af[4];
                #pragma unroll
                for (int mi = 0; mi < 4; mi++)
                    af[mi] = as4[(ki * 8 + wr * 4 + mi) * 32 + lane];
                #pragma unroll
                for (int mi = 0; mi < 4; mi++)
                    #pragma unroll
                    for (int ni = 0; ni < 8; ni++) {
                        uint32_t b0 = kh ? bf[ni].z : bf[ni].x;
                        uint32_t b1 = kh ? bf[ni].w : bf[ni].y;
                        mma16(acc[mi][ni], af[mi], b0, b1);
                    }
            }
        }
    }
    __syncthreads();

    // ---- epilogue: gates -> skewed smem -> LSTM cell -> packed fp16 h ----
    float* Cs = (float*)(smem + 1024);
    #pragma unroll
    for (int mi = 0; mi < 4; mi++)
        #pragma unroll
        for (int ni = 0; ni < 8; ni++) {
            int row0 = wr * 64 + mi * 16 + (lane >> 2);
            int col  = wc * 64 + ni * 8 + (lane & 3) * 2;
            *(float2*)&Cs[row0 * CSTR + col]       = make_float2(acc[mi][ni][0], acc[mi][ni][1]);
            *(float2*)&Cs[(row0 + 8) * CSTR + col] = make_float2(acc[mi][ni][2], acc[mi][ni][3]);
        }
    __syncthreads();

    #pragma unroll
    for (int it = 0; it < 32; it++) {
        int idx = tid + it * 256;          // 128 rows x 64 units
        int bl = idx >> 6, jl = idx & 63;
        float4 gq = *(const float4*)&Cs[bl * CSTR + jl * 4];
        int rb = nt * 256 + jl * 4;
        float gi = gq.x + bias[rb + 0];
        float gf = gq.y + bias[rb + 1];
        float gg = gq.z + bias[rb + 2];
        float go = gq.w + bias[rb + 3];
        float si = 1.0f / (1.0f + __expf(-gi));
        float sf = 1.0f / (1.0f + __expf(-gf));
        float so = 1.0f / (1.0f + __expf(-go));
        int j = nt * 64 + jl;
        size_t ci = (size_t)(mt * 128 + bl) * HID + j;
        float cn = sf * cst[ci] + si * tanhf(gg);
        cst[ci] = cn;
        float hv = so * tanhf(cn);
        Hout[(size_t)(mt * 8 + (j >> 6)) * ABLKH + a_off_h(bl, j & 63)] = __float2half_rn(hv);
    }

    __syncthreads();
    if (tid == 0) {
        #pragma unroll
        for (int s = 0; s < NSTG; s++) MBARRIER_INVAL(mb_full + s * 8);
    }
}

// ---------------- decoder (reads packed fp16 h1) ----------------
__global__ void decode_kernel(const float* __restrict__ dec_W,
                              const float* __restrict__ dec_b, int k, int wbuf) {
    int gwarp = (blockIdx.x * blockDim.x + threadIdx.x) >> 5;
    int lane = threadIdx.x & 31;
    if (gwarp >= BATCH) return;
    const __half* h1 = g_H + (size_t)(wbuf * 2 + 1) * AIMGH;
    int mt = gwarp >> 7, row = gwarp & 127;
    float a0 = 0.f, a1 = 0.f;
    #pragma unroll
    for (int j = lane; j < HID; j += 32) {
        float hv = __half2float(
            h1[(size_t)(mt * 8 + (j >> 6)) * ABLKH + a_off_h(row, j & 63)]);
        a0 += hv * dec_W[2 * j];
        a1 += hv * dec_W[2 * j + 1];
    }
    #pragma unroll
    for (int off = 16; off > 0; off >>= 1) {
        a0 += __shfl_down_sync(0xffffffffu, a0, off);
        a1 += __shfl_down_sync(0xffffffffu, a1, off);
    }
    if (lane == 0) {
        g_vel[(gwarp * PRED_N + k) * 2 + 0] = a0 + dec_b[0];
        g_vel[(gwarp * PRED_N + k) * 2 + 1] = a1 + dec_b[1];
    }
}

// ---------------- finalize ----------------
__global__ void finalize_kernel(const float* __restrict__ obs,
                                const float* __restrict__ mean,
                                const float* __restrict__ stdv,
                                float* __restrict__ out, int out_size) {
    int i = blockIdx.x * blockDim.x + threadIdx.x;
    if (i >= BATCH * 2) return;
    int b = i >> 1, d = i & 1;
    float acc = obs[(b * OBS_N + (OBS_N - 1)) * 2 + d];
    float s = stdv[d], m = mean[d];
    const int VOFF = BATCH * PRED_N * 2;
    bool write_vel = (out_size >= 2 * VOFF);
    #pragma unroll
    for (int k = 0; k < PRED_N; k++) {
        float v = g_vel[(b * PRED_N + k) * 2 + d];
        acc += v * s + m;
        out[(b * PRED_N + k) * 2 + d] = acc;
        if (write_vel) out[VOFF + (b * PRED_N + k) * 2 + d] = v;
    }
}

extern "C" void kernel_launch(void* const* d_in, const int* in_sizes, int n_in,
                              void* d_out, int out_size) {
    const float* obs    = (const float*)d_in[0];
    const float* obsVel = (const float*)d_in[1];
    const float* mean   = (const float*)d_in[2];
    const float* stdv   = (const float*)d_in[3];
    const float* enc_W  = (const float*)d_in[4];
    const float* enc_b  = (const float*)d_in[5];
    const float* dec_W  = (const float*)d_in[6];
    const float* dec_b  = (const float*)d_in[7];
    const float* Wih    = (const float*)d_in[8];
    const float* Whh    = (const float*)d_in[9];
    const float* bih    = (const float*)d_in[10];
    const float* bhh    = (const float*)d_in[11];

    cudaFuncSetAttribute(gemm_lstm_kernel,
                         cudaFuncAttributeMaxDynamicSharedMemorySize, SMEM_BYTES);

    init_state_kernel<<<(2 * AIMGH + 255) / 256, 256>>>();
    embed_kernel<<<(OBSTEPS * BH + 255) / 256, 256>>>(obsVel, mean, stdv, enc_W, enc_b);
    permute_w_kernel<<<(2 * G4 * 1024 + 255) / 256, 256>>>(Wih, Whh);
    permute_b_kernel<<<(2 * G4 + 255) / 256, 256>>>(bih, bhh);

    dim3 gg(8, 16);    // nt x mt : 128 CTAs, one wave

    for (int t = 0; t < NSTEPS; t++) {
        int w = t & 1;
        int xsel0 = (t < OBSTEPS) ? t : 7;
        gemm_lstm_kernel<<<gg, 256, SMEM_BYTES>>>(xsel0, w, 0);
        gemm_lstm_kernel<<<gg, 256, SMEM_BYTES>>>(8, w, 1);
        if (t >= OBSTEPS)
            decode_kernel<<<(BATCH * 32 + 255) / 256, 256>>>(dec_W, dec_b, t - OBSTEPS, w);
    }

    finalize_kernel<<<(BATCH * 2 + 255) / 256, 256>>>(obs, mean, stdv,
                                                      (float*)d_out, out_size);
}